// round 1
// baseline (speedup 1.0000x reference)
#include <cuda_runtime.h>

#define NB 16
#define NA 3
#define NM 32
#define NC 80
#define NH 80
#define NW 80
#define NHW (NH * NW)
#define CH (NA * (5 + NC) + NA * NM)   // 351
#define NE (NB * NA * NHW)             // 307200
#define TPB 256
#define NBLK (NE / TPB)                // 1200
#define THRESH 0.05f
#define STRIDEF 8.0f

// Scratch (allocation-free rule: __device__ globals)
__device__ float g_score[NE];
__device__ float g_cls[NE];
__device__ float g_x[NE];
__device__ float g_y[NE];
__device__ float g_w[NE];
__device__ float g_h[NE];
__device__ int   g_cnt[NBLK];
__device__ int   g_off[NBLK];

// ---------------------------------------------------------------------------
// Pass 1: decode + score + per-block keep count
// ---------------------------------------------------------------------------
__global__ void __launch_bounds__(TPB)
pass1_kernel(const float* __restrict__ in, const float* __restrict__ anchors)
{
    int e = blockIdx.x * TPB + threadIdx.x;
    int b = e / (NA * NHW);
    int r = e - b * (NA * NHW);
    int a = r / NHW;
    int p = r - a * NHW;

    const float* base = in + ((size_t)b * CH + (size_t)a * (5 + NC)) * NHW + p;

    float x0 = base[0 * NHW];
    float y0 = base[1 * NHW];
    float w0 = base[2 * NHW];
    float h0 = base[3 * NHW];
    float o0 = base[4 * NHW];

    // Online softmax over NC class logits: cls_max = 1/sum(exp(x - max)),
    // argmax of softmax == argmax of logits (first occurrence).
    float m = -1e30f, s = 0.0f;
    int idx = 0;
    const float* cb = base + 5 * NHW;
#pragma unroll 8
    for (int c = 0; c < NC; ++c) {
        float x = cb[(size_t)c * NHW];
        float mn = fmaxf(m, x);
        s = s * __expf(m - mn) + __expf(x - mn);
        if (x > m) idx = c;
        m = mn;
    }
    float cls_max = 1.0f / s;

    // Accurate exp for the threshold-critical objectness sigmoid
    float obj = 1.0f / (1.0f + expf(-o0));
    float score = cls_max * obj;

    // anchors: [NA, 2] = (w, h)
    float aw = anchors[a * 2 + 0];
    float ah = anchors[a * 2 + 1];
    float amax = fmaxf(fmaxf(fmaxf(anchors[0], anchors[1]),
                             fmaxf(anchors[2], anchors[3])),
                       fmaxf(anchors[4], anchors[5]));
    float maxv = floorf(logf(1e35f / amax / STRIDEF));

    float xs = 1.0f / (1.0f + expf(-x0)) + (float)(p % NW);
    float ys = 1.0f / (1.0f + expf(-y0)) + (float)(p / NW);
    float wv = expf(fminf(w0, maxv)) * aw;
    float hv = expf(fminf(h0, maxv)) * ah;

    g_score[e] = score;
    g_cls[e]   = (float)idx;
    g_x[e]     = xs;
    g_y[e]     = ys;
    g_w[e]     = wv;
    g_h[e]     = hv;

    // Per-block keep count
    unsigned ball = __ballot_sync(0xffffffffu, score > THRESH);
    __shared__ int wcnt[TPB / 32];
    int lane = threadIdx.x & 31;
    int warp = threadIdx.x >> 5;
    if (lane == 0) wcnt[warp] = __popc(ball);
    __syncthreads();
    if (threadIdx.x == 0) {
        int t = 0;
#pragma unroll
        for (int i = 0; i < TPB / 32; ++i) t += wcnt[i];
        g_cnt[blockIdx.x] = t;
    }
}

// ---------------------------------------------------------------------------
// Pass 2: exclusive scan of the 1200 block counts (single block, 1024 threads)
// ---------------------------------------------------------------------------
__device__ __forceinline__ int block_scan_excl_1024(int v, int* total, int* ws)
{
    int lane = threadIdx.x & 31;
    int warp = threadIdx.x >> 5;
    int inc = v;
#pragma unroll
    for (int d = 1; d < 32; d <<= 1) {
        int n = __shfl_up_sync(0xffffffffu, inc, d);
        if (lane >= d) inc += n;
    }
    if (lane == 31) ws[warp] = inc;
    __syncthreads();
    if (warp == 0) {
        int wv = ws[lane];
#pragma unroll
        for (int d = 1; d < 32; d <<= 1) {
            int n = __shfl_up_sync(0xffffffffu, wv, d);
            if (lane >= d) wv += n;
        }
        ws[lane] = wv;
    }
    __syncthreads();
    int pre = (warp > 0) ? ws[warp - 1] : 0;
    *total = ws[31];
    int excl = pre + inc - v;
    __syncthreads();  // before ws reuse
    return excl;
}

__global__ void __launch_bounds__(1024)
pass2_kernel()
{
    __shared__ int ws[32];
    int t = threadIdx.x;

    int v0 = (t < NBLK) ? g_cnt[t] : 0;
    int tot0;
    int e0 = block_scan_excl_1024(v0, &tot0, ws);
    if (t < NBLK) g_off[t] = e0;

    int t1 = t + 1024;
    int v1 = (t1 < NBLK) ? g_cnt[t1] : 0;
    int tot1;
    int e1 = block_scan_excl_1024(v1, &tot1, ws);
    if (t1 < NBLK) g_off[t1] = tot0 + e1;
}

// ---------------------------------------------------------------------------
// Pass 3: ordered compaction + row emit (mask-head gather only for kept)
// ---------------------------------------------------------------------------
__global__ void __launch_bounds__(TPB)
pass3_kernel(const float* __restrict__ in, float* __restrict__ out, long long out_size)
{
    int e = blockIdx.x * TPB + threadIdx.x;
    float score = g_score[e];
    bool keep = score > THRESH;

    unsigned ball = __ballot_sync(0xffffffffu, keep);
    int lane = threadIdx.x & 31;
    int warp = threadIdx.x >> 5;

    __shared__ int woff[TPB / 32];
    if (lane == 0) woff[warp] = __popc(ball);
    __syncthreads();
    if (threadIdx.x == 0) {
        int run = 0;
#pragma unroll
        for (int i = 0; i < TPB / 32; ++i) {
            int c = woff[i];
            woff[i] = run;
            run += c;
        }
    }
    __syncthreads();
    if (!keep) return;

    int intra = woff[warp] + __popc(ball & ((1u << lane) - 1u));
    int row = g_off[blockIdx.x] + intra;
    long long o = (long long)row * (7 + NM);
    if (o + (7 + NM) > out_size) return;  // safety guard against overflow of d_out

    int b = e / (NA * NHW);
    int r = e - b * (NA * NHW);
    int a = r / NHW;
    int p = r - a * NHW;

    out[o + 0] = (float)b;
    out[o + 1] = g_x[e] * STRIDEF;
    out[o + 2] = g_y[e] * STRIDEF;
    out[o + 3] = g_w[e] * STRIDEF;
    out[o + 4] = g_h[e] * STRIDEF;

    const float* mb = in + ((size_t)b * CH + NA * (5 + NC) + (size_t)a * NM) * NHW + p;
#pragma unroll
    for (int mi = 0; mi < NM; ++mi)
        out[o + 5 + mi] = mb[(size_t)mi * NHW];

    out[o + 5 + NM] = score;
    out[o + 6 + NM] = g_cls[e];
}

// ---------------------------------------------------------------------------
extern "C" void kernel_launch(void* const* d_in, const int* in_sizes, int n_in,
                              void* d_out, int out_size)
{
    const float* in      = (const float*)d_in[0];
    const float* anchors = (const float*)d_in[1];
    float* out = (float*)d_out;

    pass1_kernel<<<NBLK, TPB>>>(in, anchors);
    pass2_kernel<<<1, 1024>>>();
    pass3_kernel<<<NBLK, TPB>>>(in, out, (long long)out_size);
}